// round 14
// baseline (speedup 1.0000x reference)
#include <cuda_runtime.h>
#include <cstdint>

// WMeasure_Rot: elementwise quantum-measurement update.
// inputs:  d_in[0]=input f32, d_in[1]=angles f32, d_in[2]=last_res f32  (each B*N)
// output:  d_out[0:B*N) = meas_res,  d_out[B*N:2*B*N) = new_angles
//
// RNG (bit-exact): JAX threefry2x32, key=(0,42), partitionable.
// R10 = R9 (packed f32x2 float pipeline) + ALU-pipe trims:
//  * integer-domain Bernoulli test: f and thr both in [1,2) so
//    f < thr  <=>  bits < (float_bits(thr) << 9)   (exponent shifts out exactly)
//    kills the |0x3f800000 LOP3 per element. Exactly equivalent boundary.
//  * ex2 feed packed: one mul2 per pair instead of two scalar muls.
//  * threefry round 1 folded (x0 starts at 0 -> x0 = x1 rename).

#define DEVINL __device__ __forceinline__

DEVINL uint32_t rotl32(uint32_t x, int d) { return __funnelshift_l(x, x, d); }

DEVINL uint32_t threefry_bits(uint32_t ctr) {
    const uint32_t ks1 = 42u;
    const uint32_t ks2 = 0x1BD11BDAu ^ 42u;
    // x0 = 0 + ks0 = 0; round 1: x0 += x1 -> x0 = x1 (pure rename)
    uint32_t x1 = ctr + ks1;
    uint32_t x0 = x1;
    x1 = rotl32(x1, 13) ^ x0;
#define TF_ROUND(r) { x0 += x1; x1 = rotl32(x1, (r)); x1 ^= x0; }
    TF_ROUND(15) TF_ROUND(26) TF_ROUND(6)
    x0 += ks1; x1 += ks2 + 1u;
    TF_ROUND(17) TF_ROUND(29) TF_ROUND(16) TF_ROUND(24)
    x0 += ks2; x1 += 0u + 2u;
    TF_ROUND(13) TF_ROUND(15) TF_ROUND(26) TF_ROUND(6)
    x0 += 0u; x1 += ks1 + 3u;
    TF_ROUND(17) TF_ROUND(29) TF_ROUND(16) TF_ROUND(24)
    x0 += ks1; x1 += ks2 + 4u;
    TF_ROUND(13) TF_ROUND(15) TF_ROUND(26) TF_ROUND(6)
    x0 += ks2; x1 += 0u + 5u;
#undef TF_ROUND
    return x0 ^ x1;
}

DEVINL float mufu_ex2(float x)  { float r; asm("ex2.approx.f32 %0, %1;"  : "=f"(r) : "f"(x)); return r; }
DEVINL float mufu_rcp(float x)  { float r; asm("rcp.approx.f32 %0, %1;"  : "=f"(r) : "f"(x)); return r; }
DEVINL float mufu_rsq(float x)  { float r; asm("rsqrt.approx.f32 %0, %1;": "=f"(r) : "f"(x)); return r; }
DEVINL float mufu_sqrt(float x) { float r; asm("sqrt.approx.f32 %0, %1;" : "=f"(r) : "f"(x)); return r; }
DEVINL float mufu_sin(float x)  { float r; asm("sin.approx.f32 %0, %1;"  : "=f"(r) : "f"(x)); return r; }

// ---- packed f32x2 helpers (Blackwell FFMA2 path) ----
struct F2 { uint64_t v; };
DEVINL F2 pk2(float lo, float hi) { F2 r; asm("mov.b64 %0, {%1, %2};" : "=l"(r.v) : "f"(lo), "f"(hi)); return r; }
DEVINL void upk2(F2 p, float& lo, float& hi) { asm("mov.b64 {%0, %1}, %2;" : "=f"(lo), "=f"(hi) : "l"(p.v)); }
DEVINL F2 bc2(float c) { F2 r; asm("mov.b64 %0, {%1, %1};" : "=l"(r.v) : "f"(c)); return r; }
DEVINL F2 fma2(F2 a, F2 b, F2 c) { F2 d; asm("fma.rn.f32x2 %0, %1, %2, %3;" : "=l"(d.v) : "l"(a.v), "l"(b.v), "l"(c.v)); return d; }
DEVINL F2 mul2(F2 a, F2 b) { F2 d; asm("mul.rn.f32x2 %0, %1, %2;" : "=l"(d.v) : "l"(a.v), "l"(b.v)); return d; }
DEVINL F2 add2(F2 a, F2 b) { F2 d; asm("add.rn.f32x2 %0, %1, %2;" : "=l"(d.v) : "l"(a.v), "l"(b.v)); return d; }

struct Cns {
    F2 pi4, mpi4, half, pi2, msing, hsing, c15, mkhdf, kmid;
    F2 nc3, nc2, nc1, nc0, pi, flog;
};

DEVINL void wmeas_pair(F2 x2, F2 a2, F2 l2, uint32_t idx,
                       const Cns& C,
                       float& m_a, float& m_b, float& n_a, float& n_b) {
    // scalar: RNG (feeds integer compare only)
    uint32_t ba = threefry_bits(idx);
    uint32_t bb = threefry_bits(idx + 1u);

    // packed ex2 feed: x * 4/ln2
    F2 xe2 = mul2(x2, C.flog);
    float xea, xeb; upk2(xe2, xea, xeb);
    float ea = mufu_ex2(xea);
    float eb = mufu_ex2(xeb);
    float ra = mufu_rcp(ea + 1.0f);
    float rb = mufu_rcp(eb + 1.0f);

    // packed: ht = 0.5*a + fma(pi/4, lr, -pi/4) + (pi/2)*r
    F2 r2  = pk2(ra, rb);
    F2 bk2 = fma2(C.pi4, l2, C.mpi4);       // exact for lr in {+1,-1}
    F2 b22 = fma2(C.half, a2, bk2);
    F2 ht2 = fma2(C.pi2, r2, b22);

    float hta, htb; upk2(ht2, hta, htb);
    float sa = mufu_sin(hta);
    float sb = mufu_sin(htb);

    F2 s2   = pk2(sa, sb);
    F2 gs2  = mul2(C.msing, s2);            // -SIN_G * s
    F2 hez2 = fma2(gs2, s2, C.hsing);       // (sin g * cos t)/2
    F2 thr2 = add2(hez2, C.c15);            // thr = 1.5 + hez, in [1.146,1.854]

    // integer-domain Bernoulli: f < thr  <=>  bits < (thr_bits << 9)
    float ta, tb; upk2(thr2, ta, tb);
    float mea = (ba < (__float_as_uint(ta) << 9)) ? 1.0f : -1.0f;
    float meb = (bb < (__float_as_uint(tb) << 9)) ? 1.0f : -1.0f;

    F2 ms2 = pk2(mea, meb);
    F2 p2  = fma2(ms2, hez2, C.half);       // (1+meas*ez)/2 in [0.146,0.854]
    F2 K2  = fma2(ms2, C.mkhdf, C.kmid);

    float pa, pb; upk2(p2, pa, pb);
    float qa = mufu_rsq(pa);
    float qb = mufu_rsq(pb);

    F2 q2  = pk2(qa, qb);
    F2 sk2 = mul2(s2, K2);
    F2 sd2 = mul2(sk2, q2);                 // side

    float sda, sdb; upk2(sd2, sda, sdb);
    float aaa = fminf(fabsf(sda), 1.0f);
    float aab = fminf(fabsf(sdb), 1.0f);
    float sqa = mufu_sqrt(1.0f - aaa);
    float sqb = mufu_sqrt(1.0f - aab);

    // packed asin tail: negated-coefficient Horner absorbs the -sq
    F2 aa2 = pk2(aaa, aab);
    F2 sq2 = pk2(sqa, sqb);
    F2 po  = fma2(C.nc3, aa2, C.nc2);
    po     = fma2(po,    aa2, C.nc1);
    po     = fma2(po,    aa2, C.nc0);
    F2 v2  = fma2(sq2, po, C.pi);

    float va, vb; upk2(v2, va, vb);
    m_a = mea;
    m_b = meb;
    n_a = copysignf(va, sda);
    n_b = copysignf(vb, sdb);
}

__global__ void __launch_bounds__(256)
wmeasure_rot_kernel(const float4* __restrict__ inp,
                    const float4* __restrict__ ang,
                    const float4* __restrict__ lres,
                    float4* __restrict__ out_meas,
                    float4* __restrict__ out_ang) {
    Cns C;
    C.pi4   = bc2( 0.7853981633974483f);
    C.mpi4  = bc2(-0.7853981633974483f);
    C.half  = bc2( 0.5f);
    C.pi2   = bc2( 1.5707963267948966f);
    C.msing = bc2(-0.70710678f);
    C.hsing = bc2( 0.35355339f);
    C.c15   = bc2( 1.5f);
    C.mkhdf = bc2(-0.2705980500730985f);
    C.kmid  = bc2( 0.6532814824381883f);
    C.nc3   = bc2( 0.0374586f);             // negated doubled coefficients
    C.nc2   = bc2(-0.1485220f);
    C.nc1   = bc2( 0.4242288f);
    C.nc0   = bc2(-3.1414576f);
    C.pi    = bc2( 3.14159265358979f);
    C.flog  = bc2( 5.770780163555852f);     // 4/ln(2)

    int t = blockIdx.x * blockDim.x + threadIdx.x;
    int s0 = 2 * t;
    int s1 = 2 * t + 1;
    uint32_t base = (uint32_t)t * 8u;

    float4 x0 = inp[s0],  x1 = inp[s1];
    float4 a0 = ang[s0],  a1 = ang[s1];
    float4 l0 = lres[s0], l1 = lres[s1];

    float m[8], n[8];
    wmeas_pair(pk2(x0.x, x0.y), pk2(a0.x, a0.y), pk2(l0.x, l0.y), base + 0u, C, m[0], m[1], n[0], n[1]);
    wmeas_pair(pk2(x0.z, x0.w), pk2(a0.z, a0.w), pk2(l0.z, l0.w), base + 2u, C, m[2], m[3], n[2], n[3]);
    wmeas_pair(pk2(x1.x, x1.y), pk2(a1.x, a1.y), pk2(l1.x, l1.y), base + 4u, C, m[4], m[5], n[4], n[5]);
    wmeas_pair(pk2(x1.z, x1.w), pk2(a1.z, a1.w), pk2(l1.z, l1.w), base + 6u, C, m[6], m[7], n[6], n[7]);

    out_meas[s0] = make_float4(m[0], m[1], m[2], m[3]);
    out_meas[s1] = make_float4(m[4], m[5], m[6], m[7]);
    out_ang[s0]  = make_float4(n[0], n[1], n[2], n[3]);
    out_ang[s1]  = make_float4(n[4], n[5], n[6], n[7]);
}

extern "C" void kernel_launch(void* const* d_in, const int* in_sizes, int n_in,
                              void* d_out, int out_size) {
    const float* inp  = (const float*)d_in[0];
    const float* ang  = (const float*)d_in[1];
    const float* lres = (const float*)d_in[2];
    float* out = (float*)d_out;

    int n = in_sizes[0];                 // B*N = 33554432 (divisible by 2048)
    int threads = n / 8;
    int block = 256;
    int grid = (threads + block - 1) / block;

    wmeasure_rot_kernel<<<grid, block>>>(
        (const float4*)inp, (const float4*)ang, (const float4*)lres,
        (float4*)out, (float4*)(out + n));
}

// round 15
// speedup vs baseline: 1.0026x; 1.0026x over previous
#include <cuda_runtime.h>
#include <cstdint>

// WMeasure_Rot: elementwise quantum-measurement update.
// inputs:  d_in[0]=input f32, d_in[1]=angles f32, d_in[2]=last_res f32  (each B*N)
// output:  d_out[0:B*N) = meas_res,  d_out[B*N:2*B*N) = new_angles
//
// RNG (bit-exact): JAX threefry2x32, key=(0,42), partitionable.
// R10 = R9 (packed f32x2 float pipeline) + ALU-pipe trims:
//  * integer-domain Bernoulli test: f and thr both in [1,2) so
//    f < thr  <=>  bits < (float_bits(thr) << 9)   (exponent shifts out exactly)
//    kills the |0x3f800000 LOP3 per element. Exactly equivalent boundary.
//  * ex2 feed packed: one mul2 per pair instead of two scalar muls.
//  * threefry round 1 folded (x0 starts at 0 -> x0 = x1 rename).

#define DEVINL __device__ __forceinline__

DEVINL uint32_t rotl32(uint32_t x, int d) { return __funnelshift_l(x, x, d); }

DEVINL uint32_t threefry_bits(uint32_t ctr) {
    const uint32_t ks1 = 42u;
    const uint32_t ks2 = 0x1BD11BDAu ^ 42u;
    // x0 = 0 + ks0 = 0; round 1: x0 += x1 -> x0 = x1 (pure rename)
    uint32_t x1 = ctr + ks1;
    uint32_t x0 = x1;
    x1 = rotl32(x1, 13) ^ x0;
#define TF_ROUND(r) { x0 += x1; x1 = rotl32(x1, (r)); x1 ^= x0; }
    TF_ROUND(15) TF_ROUND(26) TF_ROUND(6)
    x0 += ks1; x1 += ks2 + 1u;
    TF_ROUND(17) TF_ROUND(29) TF_ROUND(16) TF_ROUND(24)
    x0 += ks2; x1 += 0u + 2u;
    TF_ROUND(13) TF_ROUND(15) TF_ROUND(26) TF_ROUND(6)
    x0 += 0u; x1 += ks1 + 3u;
    TF_ROUND(17) TF_ROUND(29) TF_ROUND(16) TF_ROUND(24)
    x0 += ks1; x1 += ks2 + 4u;
    TF_ROUND(13) TF_ROUND(15) TF_ROUND(26) TF_ROUND(6)
    x0 += ks2; x1 += 0u + 5u;
#undef TF_ROUND
    return x0 ^ x1;
}

DEVINL float mufu_ex2(float x)  { float r; asm("ex2.approx.f32 %0, %1;"  : "=f"(r) : "f"(x)); return r; }
DEVINL float mufu_rcp(float x)  { float r; asm("rcp.approx.f32 %0, %1;"  : "=f"(r) : "f"(x)); return r; }
DEVINL float mufu_rsq(float x)  { float r; asm("rsqrt.approx.f32 %0, %1;": "=f"(r) : "f"(x)); return r; }
DEVINL float mufu_sqrt(float x) { float r; asm("sqrt.approx.f32 %0, %1;" : "=f"(r) : "f"(x)); return r; }
DEVINL float mufu_sin(float x)  { float r; asm("sin.approx.f32 %0, %1;"  : "=f"(r) : "f"(x)); return r; }

// ---- packed f32x2 helpers (Blackwell FFMA2 path) ----
struct F2 { uint64_t v; };
DEVINL F2 pk2(float lo, float hi) { F2 r; asm("mov.b64 %0, {%1, %2};" : "=l"(r.v) : "f"(lo), "f"(hi)); return r; }
DEVINL void upk2(F2 p, float& lo, float& hi) { asm("mov.b64 {%0, %1}, %2;" : "=f"(lo), "=f"(hi) : "l"(p.v)); }
DEVINL F2 bc2(float c) { F2 r; asm("mov.b64 %0, {%1, %1};" : "=l"(r.v) : "f"(c)); return r; }
DEVINL F2 fma2(F2 a, F2 b, F2 c) { F2 d; asm("fma.rn.f32x2 %0, %1, %2, %3;" : "=l"(d.v) : "l"(a.v), "l"(b.v), "l"(c.v)); return d; }
DEVINL F2 mul2(F2 a, F2 b) { F2 d; asm("mul.rn.f32x2 %0, %1, %2;" : "=l"(d.v) : "l"(a.v), "l"(b.v)); return d; }
DEVINL F2 add2(F2 a, F2 b) { F2 d; asm("add.rn.f32x2 %0, %1, %2;" : "=l"(d.v) : "l"(a.v), "l"(b.v)); return d; }

struct Cns {
    F2 pi4, mpi4, half, pi2, msing, hsing, c15, mkhdf, kmid;
    F2 nc3, nc2, nc1, nc0, pi, flog;
};

DEVINL void wmeas_pair(F2 x2, F2 a2, F2 l2, uint32_t idx,
                       const Cns& C,
                       float& m_a, float& m_b, float& n_a, float& n_b) {
    // scalar: RNG (feeds integer compare only)
    uint32_t ba = threefry_bits(idx);
    uint32_t bb = threefry_bits(idx + 1u);

    // packed ex2 feed: x * 4/ln2
    F2 xe2 = mul2(x2, C.flog);
    float xea, xeb; upk2(xe2, xea, xeb);
    float ea = mufu_ex2(xea);
    float eb = mufu_ex2(xeb);
    float ra = mufu_rcp(ea + 1.0f);
    float rb = mufu_rcp(eb + 1.0f);

    // packed: ht = 0.5*a + fma(pi/4, lr, -pi/4) + (pi/2)*r
    F2 r2  = pk2(ra, rb);
    F2 bk2 = fma2(C.pi4, l2, C.mpi4);       // exact for lr in {+1,-1}
    F2 b22 = fma2(C.half, a2, bk2);
    F2 ht2 = fma2(C.pi2, r2, b22);

    float hta, htb; upk2(ht2, hta, htb);
    float sa = mufu_sin(hta);
    float sb = mufu_sin(htb);

    F2 s2   = pk2(sa, sb);
    F2 gs2  = mul2(C.msing, s2);            // -SIN_G * s
    F2 hez2 = fma2(gs2, s2, C.hsing);       // (sin g * cos t)/2
    F2 thr2 = add2(hez2, C.c15);            // thr = 1.5 + hez, in [1.146,1.854]

    // integer-domain Bernoulli: f < thr  <=>  bits < (thr_bits << 9)
    float ta, tb; upk2(thr2, ta, tb);
    float mea = (ba < (__float_as_uint(ta) << 9)) ? 1.0f : -1.0f;
    float meb = (bb < (__float_as_uint(tb) << 9)) ? 1.0f : -1.0f;

    F2 ms2 = pk2(mea, meb);
    F2 p2  = fma2(ms2, hez2, C.half);       // (1+meas*ez)/2 in [0.146,0.854]
    F2 K2  = fma2(ms2, C.mkhdf, C.kmid);

    float pa, pb; upk2(p2, pa, pb);
    float qa = mufu_rsq(pa);
    float qb = mufu_rsq(pb);

    F2 q2  = pk2(qa, qb);
    F2 sk2 = mul2(s2, K2);
    F2 sd2 = mul2(sk2, q2);                 // side

    float sda, sdb; upk2(sd2, sda, sdb);
    float aaa = fminf(fabsf(sda), 1.0f);
    float aab = fminf(fabsf(sdb), 1.0f);
    float sqa = mufu_sqrt(1.0f - aaa);
    float sqb = mufu_sqrt(1.0f - aab);

    // packed asin tail: negated-coefficient Horner absorbs the -sq
    F2 aa2 = pk2(aaa, aab);
    F2 sq2 = pk2(sqa, sqb);
    F2 po  = fma2(C.nc3, aa2, C.nc2);
    po     = fma2(po,    aa2, C.nc1);
    po     = fma2(po,    aa2, C.nc0);
    F2 v2  = fma2(sq2, po, C.pi);

    float va, vb; upk2(v2, va, vb);
    m_a = mea;
    m_b = meb;
    n_a = copysignf(va, sda);
    n_b = copysignf(vb, sdb);
}

__global__ void __launch_bounds__(256)
wmeasure_rot_kernel(const float4* __restrict__ inp,
                    const float4* __restrict__ ang,
                    const float4* __restrict__ lres,
                    float4* __restrict__ out_meas,
                    float4* __restrict__ out_ang) {
    Cns C;
    C.pi4   = bc2( 0.7853981633974483f);
    C.mpi4  = bc2(-0.7853981633974483f);
    C.half  = bc2( 0.5f);
    C.pi2   = bc2( 1.5707963267948966f);
    C.msing = bc2(-0.70710678f);
    C.hsing = bc2( 0.35355339f);
    C.c15   = bc2( 1.5f);
    C.mkhdf = bc2(-0.2705980500730985f);
    C.kmid  = bc2( 0.6532814824381883f);
    C.nc3   = bc2( 0.0374586f);             // negated doubled coefficients
    C.nc2   = bc2(-0.1485220f);
    C.nc1   = bc2( 0.4242288f);
    C.nc0   = bc2(-3.1414576f);
    C.pi    = bc2( 3.14159265358979f);
    C.flog  = bc2( 5.770780163555852f);     // 4/ln(2)

    int t = blockIdx.x * blockDim.x + threadIdx.x;
    int s0 = 2 * t;
    int s1 = 2 * t + 1;
    uint32_t base = (uint32_t)t * 8u;

    float4 x0 = inp[s0],  x1 = inp[s1];
    float4 a0 = ang[s0],  a1 = ang[s1];
    float4 l0 = lres[s0], l1 = lres[s1];

    float m[8], n[8];
    wmeas_pair(pk2(x0.x, x0.y), pk2(a0.x, a0.y), pk2(l0.x, l0.y), base + 0u, C, m[0], m[1], n[0], n[1]);
    wmeas_pair(pk2(x0.z, x0.w), pk2(a0.z, a0.w), pk2(l0.z, l0.w), base + 2u, C, m[2], m[3], n[2], n[3]);
    wmeas_pair(pk2(x1.x, x1.y), pk2(a1.x, a1.y), pk2(l1.x, l1.y), base + 4u, C, m[4], m[5], n[4], n[5]);
    wmeas_pair(pk2(x1.z, x1.w), pk2(a1.z, a1.w), pk2(l1.z, l1.w), base + 6u, C, m[6], m[7], n[6], n[7]);

    out_meas[s0] = make_float4(m[0], m[1], m[2], m[3]);
    out_meas[s1] = make_float4(m[4], m[5], m[6], m[7]);
    out_ang[s0]  = make_float4(n[0], n[1], n[2], n[3]);
    out_ang[s1]  = make_float4(n[4], n[5], n[6], n[7]);
}

extern "C" void kernel_launch(void* const* d_in, const int* in_sizes, int n_in,
                              void* d_out, int out_size) {
    const float* inp  = (const float*)d_in[0];
    const float* ang  = (const float*)d_in[1];
    const float* lres = (const float*)d_in[2];
    float* out = (float*)d_out;

    int n = in_sizes[0];                 // B*N = 33554432 (divisible by 2048)
    int threads = n / 8;
    int block = 256;
    int grid = (threads + block - 1) / block;

    wmeasure_rot_kernel<<<grid, block>>>(
        (const float4*)inp, (const float4*)ang, (const float4*)lres,
        (float4*)out, (float4*)(out + n));
}

// round 16
// speedup vs baseline: 1.0035x; 1.0009x over previous
#include <cuda_runtime.h>
#include <cstdint>

// WMeasure_Rot: elementwise quantum-measurement update.
// inputs:  d_in[0]=input f32, d_in[1]=angles f32, d_in[2]=last_res f32  (each B*N)
// output:  d_out[0:B*N) = meas_res,  d_out[B*N:2*B*N) = new_angles
//
// RNG (bit-exact): JAX threefry2x32, key=(0,42), partitionable.
// R10 = R9 (packed f32x2 float pipeline) + ALU-pipe trims:
//  * integer-domain Bernoulli test: f and thr both in [1,2) so
//    f < thr  <=>  bits < (float_bits(thr) << 9)   (exponent shifts out exactly)
//    kills the |0x3f800000 LOP3 per element. Exactly equivalent boundary.
//  * ex2 feed packed: one mul2 per pair instead of two scalar muls.
//  * threefry round 1 folded (x0 starts at 0 -> x0 = x1 rename).

#define DEVINL __device__ __forceinline__

DEVINL uint32_t rotl32(uint32_t x, int d) { return __funnelshift_l(x, x, d); }

DEVINL uint32_t threefry_bits(uint32_t ctr) {
    const uint32_t ks1 = 42u;
    const uint32_t ks2 = 0x1BD11BDAu ^ 42u;
    // x0 = 0 + ks0 = 0; round 1: x0 += x1 -> x0 = x1 (pure rename)
    uint32_t x1 = ctr + ks1;
    uint32_t x0 = x1;
    x1 = rotl32(x1, 13) ^ x0;
#define TF_ROUND(r) { x0 += x1; x1 = rotl32(x1, (r)); x1 ^= x0; }
    TF_ROUND(15) TF_ROUND(26) TF_ROUND(6)
    x0 += ks1; x1 += ks2 + 1u;
    TF_ROUND(17) TF_ROUND(29) TF_ROUND(16) TF_ROUND(24)
    x0 += ks2; x1 += 0u + 2u;
    TF_ROUND(13) TF_ROUND(15) TF_ROUND(26) TF_ROUND(6)
    x0 += 0u; x1 += ks1 + 3u;
    TF_ROUND(17) TF_ROUND(29) TF_ROUND(16) TF_ROUND(24)
    x0 += ks1; x1 += ks2 + 4u;
    TF_ROUND(13) TF_ROUND(15) TF_ROUND(26) TF_ROUND(6)
    x0 += ks2; x1 += 0u + 5u;
#undef TF_ROUND
    return x0 ^ x1;
}

DEVINL float mufu_ex2(float x)  { float r; asm("ex2.approx.f32 %0, %1;"  : "=f"(r) : "f"(x)); return r; }
DEVINL float mufu_rcp(float x)  { float r; asm("rcp.approx.f32 %0, %1;"  : "=f"(r) : "f"(x)); return r; }
DEVINL float mufu_rsq(float x)  { float r; asm("rsqrt.approx.f32 %0, %1;": "=f"(r) : "f"(x)); return r; }
DEVINL float mufu_sqrt(float x) { float r; asm("sqrt.approx.f32 %0, %1;" : "=f"(r) : "f"(x)); return r; }
DEVINL float mufu_sin(float x)  { float r; asm("sin.approx.f32 %0, %1;"  : "=f"(r) : "f"(x)); return r; }

// ---- packed f32x2 helpers (Blackwell FFMA2 path) ----
struct F2 { uint64_t v; };
DEVINL F2 pk2(float lo, float hi) { F2 r; asm("mov.b64 %0, {%1, %2};" : "=l"(r.v) : "f"(lo), "f"(hi)); return r; }
DEVINL void upk2(F2 p, float& lo, float& hi) { asm("mov.b64 {%0, %1}, %2;" : "=f"(lo), "=f"(hi) : "l"(p.v)); }
DEVINL F2 bc2(float c) { F2 r; asm("mov.b64 %0, {%1, %1};" : "=l"(r.v) : "f"(c)); return r; }
DEVINL F2 fma2(F2 a, F2 b, F2 c) { F2 d; asm("fma.rn.f32x2 %0, %1, %2, %3;" : "=l"(d.v) : "l"(a.v), "l"(b.v), "l"(c.v)); return d; }
DEVINL F2 mul2(F2 a, F2 b) { F2 d; asm("mul.rn.f32x2 %0, %1, %2;" : "=l"(d.v) : "l"(a.v), "l"(b.v)); return d; }
DEVINL F2 add2(F2 a, F2 b) { F2 d; asm("add.rn.f32x2 %0, %1, %2;" : "=l"(d.v) : "l"(a.v), "l"(b.v)); return d; }

struct Cns {
    F2 pi4, mpi4, half, pi2, msing, hsing, c15, mkhdf, kmid;
    F2 nc3, nc2, nc1, nc0, pi, flog;
};

DEVINL void wmeas_pair(F2 x2, F2 a2, F2 l2, uint32_t idx,
                       const Cns& C,
                       float& m_a, float& m_b, float& n_a, float& n_b) {
    // scalar: RNG (feeds integer compare only)
    uint32_t ba = threefry_bits(idx);
    uint32_t bb = threefry_bits(idx + 1u);

    // packed ex2 feed: x * 4/ln2
    F2 xe2 = mul2(x2, C.flog);
    float xea, xeb; upk2(xe2, xea, xeb);
    float ea = mufu_ex2(xea);
    float eb = mufu_ex2(xeb);
    float ra = mufu_rcp(ea + 1.0f);
    float rb = mufu_rcp(eb + 1.0f);

    // packed: ht = 0.5*a + fma(pi/4, lr, -pi/4) + (pi/2)*r
    F2 r2  = pk2(ra, rb);
    F2 bk2 = fma2(C.pi4, l2, C.mpi4);       // exact for lr in {+1,-1}
    F2 b22 = fma2(C.half, a2, bk2);
    F2 ht2 = fma2(C.pi2, r2, b22);

    float hta, htb; upk2(ht2, hta, htb);
    float sa = mufu_sin(hta);
    float sb = mufu_sin(htb);

    F2 s2   = pk2(sa, sb);
    F2 gs2  = mul2(C.msing, s2);            // -SIN_G * s
    F2 hez2 = fma2(gs2, s2, C.hsing);       // (sin g * cos t)/2
    F2 thr2 = add2(hez2, C.c15);            // thr = 1.5 + hez, in [1.146,1.854]

    // integer-domain Bernoulli: f < thr  <=>  bits < (thr_bits << 9)
    float ta, tb; upk2(thr2, ta, tb);
    float mea = (ba < (__float_as_uint(ta) << 9)) ? 1.0f : -1.0f;
    float meb = (bb < (__float_as_uint(tb) << 9)) ? 1.0f : -1.0f;

    F2 ms2 = pk2(mea, meb);
    F2 p2  = fma2(ms2, hez2, C.half);       // (1+meas*ez)/2 in [0.146,0.854]
    F2 K2  = fma2(ms2, C.mkhdf, C.kmid);

    float pa, pb; upk2(p2, pa, pb);
    float qa = mufu_rsq(pa);
    float qb = mufu_rsq(pb);

    F2 q2  = pk2(qa, qb);
    F2 sk2 = mul2(s2, K2);
    F2 sd2 = mul2(sk2, q2);                 // side

    float sda, sdb; upk2(sd2, sda, sdb);
    float aaa = fminf(fabsf(sda), 1.0f);
    float aab = fminf(fabsf(sdb), 1.0f);
    float sqa = mufu_sqrt(1.0f - aaa);
    float sqb = mufu_sqrt(1.0f - aab);

    // packed asin tail: negated-coefficient Horner absorbs the -sq
    F2 aa2 = pk2(aaa, aab);
    F2 sq2 = pk2(sqa, sqb);
    F2 po  = fma2(C.nc3, aa2, C.nc2);
    po     = fma2(po,    aa2, C.nc1);
    po     = fma2(po,    aa2, C.nc0);
    F2 v2  = fma2(sq2, po, C.pi);

    float va, vb; upk2(v2, va, vb);
    m_a = mea;
    m_b = meb;
    n_a = copysignf(va, sda);
    n_b = copysignf(vb, sdb);
}

__global__ void __launch_bounds__(256)
wmeasure_rot_kernel(const float4* __restrict__ inp,
                    const float4* __restrict__ ang,
                    const float4* __restrict__ lres,
                    float4* __restrict__ out_meas,
                    float4* __restrict__ out_ang) {
    Cns C;
    C.pi4   = bc2( 0.7853981633974483f);
    C.mpi4  = bc2(-0.7853981633974483f);
    C.half  = bc2( 0.5f);
    C.pi2   = bc2( 1.5707963267948966f);
    C.msing = bc2(-0.70710678f);
    C.hsing = bc2( 0.35355339f);
    C.c15   = bc2( 1.5f);
    C.mkhdf = bc2(-0.2705980500730985f);
    C.kmid  = bc2( 0.6532814824381883f);
    C.nc3   = bc2( 0.0374586f);             // negated doubled coefficients
    C.nc2   = bc2(-0.1485220f);
    C.nc1   = bc2( 0.4242288f);
    C.nc0   = bc2(-3.1414576f);
    C.pi    = bc2( 3.14159265358979f);
    C.flog  = bc2( 5.770780163555852f);     // 4/ln(2)

    int t = blockIdx.x * blockDim.x + threadIdx.x;
    int s0 = 2 * t;
    int s1 = 2 * t + 1;
    uint32_t base = (uint32_t)t * 8u;

    float4 x0 = inp[s0],  x1 = inp[s1];
    float4 a0 = ang[s0],  a1 = ang[s1];
    float4 l0 = lres[s0], l1 = lres[s1];

    float m[8], n[8];
    wmeas_pair(pk2(x0.x, x0.y), pk2(a0.x, a0.y), pk2(l0.x, l0.y), base + 0u, C, m[0], m[1], n[0], n[1]);
    wmeas_pair(pk2(x0.z, x0.w), pk2(a0.z, a0.w), pk2(l0.z, l0.w), base + 2u, C, m[2], m[3], n[2], n[3]);
    wmeas_pair(pk2(x1.x, x1.y), pk2(a1.x, a1.y), pk2(l1.x, l1.y), base + 4u, C, m[4], m[5], n[4], n[5]);
    wmeas_pair(pk2(x1.z, x1.w), pk2(a1.z, a1.w), pk2(l1.z, l1.w), base + 6u, C, m[6], m[7], n[6], n[7]);

    out_meas[s0] = make_float4(m[0], m[1], m[2], m[3]);
    out_meas[s1] = make_float4(m[4], m[5], m[6], m[7]);
    out_ang[s0]  = make_float4(n[0], n[1], n[2], n[3]);
    out_ang[s1]  = make_float4(n[4], n[5], n[6], n[7]);
}

extern "C" void kernel_launch(void* const* d_in, const int* in_sizes, int n_in,
                              void* d_out, int out_size) {
    const float* inp  = (const float*)d_in[0];
    const float* ang  = (const float*)d_in[1];
    const float* lres = (const float*)d_in[2];
    float* out = (float*)d_out;

    int n = in_sizes[0];                 // B*N = 33554432 (divisible by 2048)
    int threads = n / 8;
    int block = 256;
    int grid = (threads + block - 1) / block;

    wmeasure_rot_kernel<<<grid, block>>>(
        (const float4*)inp, (const float4*)ang, (const float4*)lres,
        (float4*)out, (float4*)(out + n));
}